// round 1
// baseline (speedup 1.0000x reference)
#include <cuda_runtime.h>

#define H 128
#define NMAX 100000
#define EMAX 1600000
#define NG 512

// ---- scratch (static __device__ globals; no allocation allowed) ----
__device__ float g_hA[(size_t)NMAX * H];
__device__ float g_hB[(size_t)NMAX * H];
__device__ float g_t[(size_t)NMAX * H];
__device__ float g_dinv[NMAX];
__device__ int   g_count[NMAX];
__device__ int   g_fill[NMAX];
__device__ int   g_rowptr[NMAX + 1];
__device__ int   g_src[EMAX];
__device__ int   g_gptr[NG + 1];
__device__ float g_p[NG * 5 * H];
__device__ float g_q[NG * 5 * H];

// ---- preprocessing kernels ----
__global__ void k_init(int n) {
    int i = blockIdx.x * blockDim.x + threadIdx.x;
    if (i < n) { g_count[i] = 0; g_fill[i] = 0; }
    if (i <= NG) g_gptr[i] = n;
}

__global__ void k_hist(const int* __restrict__ col, int E) {
    int i = blockIdx.x * blockDim.x + threadIdx.x;
    if (i < E) atomicAdd(&g_count[col[i]], 1);
}

__global__ void k_dinv(int n) {
    int i = blockIdx.x * blockDim.x + threadIdx.x;
    if (i < n) g_dinv[i] = rsqrtf((float)(g_count[i] + 1));  // +1 self loop
}

// single-block exclusive scan over g_count -> g_rowptr
__global__ void k_scan(int n) {
    __shared__ int sd[1024];
    int tid = threadIdx.x;
    int offset = 0;
    for (int base = 0; base < n; base += 1024) {
        int v = (base + tid < n) ? g_count[base + tid] : 0;
        sd[tid] = v;
        __syncthreads();
        for (int d = 1; d < 1024; d <<= 1) {
            int t = (tid >= d) ? sd[tid - d] : 0;
            __syncthreads();
            sd[tid] += t;
            __syncthreads();
        }
        if (base + tid < n) g_rowptr[base + tid] = offset + sd[tid] - v;
        int tot = sd[1023];
        __syncthreads();
        offset += tot;
    }
    if (tid == 0) g_rowptr[n] = offset;
}

__global__ void k_scatter(const int* __restrict__ row, const int* __restrict__ col, int E) {
    int i = blockIdx.x * blockDim.x + threadIdx.x;
    if (i < E) {
        int c = col[i];
        int pos = g_rowptr[c] + atomicAdd(&g_fill[c], 1);
        g_src[pos] = row[i];
    }
}

__global__ void k_gmin(const int* __restrict__ batch, int n) {
    int i = blockIdx.x * blockDim.x + threadIdx.x;
    if (i < n) atomicMin(&g_gptr[batch[i]], i);
}

__global__ void k_gfix() {
    for (int g = NG - 1; g >= 0; --g)
        if (g_gptr[g] > g_gptr[g + 1]) g_gptr[g] = g_gptr[g + 1];
}

// ---- GEMM: C[nrows,128] = A[nrows,128] @ W[128,128] ----
__global__ __launch_bounds__(256) void k_gemm(const float* __restrict__ A,
                                              const float* __restrict__ W,
                                              float* __restrict__ C, int nrows) {
    __shared__ float As[128][33];
    __shared__ float Ws[32][H];
    int m0 = blockIdx.x * 128;
    int tid = threadIdx.x;
    int tx = tid & 15, ty = tid >> 4;

    float acc[8][8];
#pragma unroll
    for (int i = 0; i < 8; i++)
#pragma unroll
        for (int j = 0; j < 8; j++) acc[i][j] = 0.f;

    int lr = tid >> 3;          // 0..31
    int lc = (tid & 7) << 2;    // 0,4,...,28

    for (int k0 = 0; k0 < H; k0 += 32) {
#pragma unroll
        for (int p = 0; p < 4; p++) {
            int m = m0 + p * 32 + lr;
            float4 v = make_float4(0.f, 0.f, 0.f, 0.f);
            if (m < nrows) v = *(const float4*)&A[(size_t)m * H + k0 + lc];
            As[p * 32 + lr][lc + 0] = v.x;
            As[p * 32 + lr][lc + 1] = v.y;
            As[p * 32 + lr][lc + 2] = v.z;
            As[p * 32 + lr][lc + 3] = v.w;
        }
        {
            int wr = tid >> 5;          // 0..7
            int wc = (tid & 31) << 2;   // 0..124
#pragma unroll
            for (int p = 0; p < 4; p++) {
                int kk = p * 8 + wr;
                *(float4*)&Ws[kk][wc] = *(const float4*)&W[(size_t)(k0 + kk) * H + wc];
            }
        }
        __syncthreads();
#pragma unroll
        for (int kk = 0; kk < 32; ++kk) {
            float a[8], b[8];
#pragma unroll
            for (int i = 0; i < 8; i++) a[i] = As[ty * 8 + i][kk];
            float4 b0 = *(const float4*)&Ws[kk][tx * 8];
            float4 b1 = *(const float4*)&Ws[kk][tx * 8 + 4];
            b[0] = b0.x; b[1] = b0.y; b[2] = b0.z; b[3] = b0.w;
            b[4] = b1.x; b[5] = b1.y; b[6] = b1.z; b[7] = b1.w;
#pragma unroll
            for (int i = 0; i < 8; i++)
#pragma unroll
                for (int j = 0; j < 8; j++) acc[i][j] = fmaf(a[i], b[j], acc[i][j]);
        }
        __syncthreads();
    }
#pragma unroll
    for (int i = 0; i < 8; i++) {
        int m = m0 + ty * 8 + i;
        if (m < nrows) {
            float4 v0 = make_float4(acc[i][0], acc[i][1], acc[i][2], acc[i][3]);
            float4 v1 = make_float4(acc[i][4], acc[i][5], acc[i][6], acc[i][7]);
            *(float4*)&C[(size_t)m * H + tx * 8] = v0;
            *(float4*)&C[(size_t)m * H + tx * 8 + 4] = v1;
        }
    }
}

// ---- SpMM: h[i] = relu(dinv[i]*sum_e dinv[src]*t[src] + dinv[i]^2*t[i] + b) ----
__global__ __launch_bounds__(256) void k_spmm(const float* __restrict__ t,
                                              const float* __restrict__ bias,
                                              float* __restrict__ h, int n) {
    int warp = (blockIdx.x * blockDim.x + threadIdx.x) >> 5;
    if (warp >= n) return;
    int lane = threadIdx.x & 31;
    const float4* t4 = (const float4*)t;

    float di = g_dinv[warp];
    float4 self = t4[(size_t)warp * 32 + lane];
    float ax = 0.f, ay = 0.f, az = 0.f, aw = 0.f;
    int e0 = g_rowptr[warp], e1 = g_rowptr[warp + 1];
    for (int e = e0; e < e1; ++e) {
        int s = g_src[e];
        float w = g_dinv[s];
        float4 v = t4[(size_t)s * 32 + lane];
        ax = fmaf(w, v.x, ax);
        ay = fmaf(w, v.y, ay);
        az = fmaf(w, v.z, az);
        aw = fmaf(w, v.w, aw);
    }
    float s2 = di * di;
    float4 b = ((const float4*)bias)[lane];
    float4 r;
    r.x = fmaxf(fmaf(di, ax, fmaf(s2, self.x, b.x)), 0.f);
    r.y = fmaxf(fmaf(di, ay, fmaf(s2, self.y, b.y)), 0.f);
    r.z = fmaxf(fmaf(di, az, fmaf(s2, self.z, b.z)), 0.f);
    r.w = fmaxf(fmaf(di, aw, fmaf(s2, self.w, b.w)), 0.f);
    ((float4*)h)[(size_t)warp * 32 + lane] = r;
}

// ---- global mean pool (batch is sorted -> contiguous ranges) ----
__global__ void k_pool(const float* __restrict__ h, int off) {
    int g = blockIdx.x, tx = threadIdx.x;
    int s = g_gptr[g], e = g_gptr[g + 1];
    float sum = 0.f;
    for (int i = s; i < e; ++i) sum += h[(size_t)i * H + tx];
    int cnt = e - s;
    g_p[g * (5 * H) + off + tx] = sum / (float)(cnt > 0 ? cnt : 1);
}

// ---- MLP head ----
__global__ void k_mlp1(const float* __restrict__ Wl1, const float* __restrict__ bl1) {
    __shared__ float ps[5 * H];
    int g = blockIdx.y;
    int j = blockIdx.x * H + threadIdx.x;
    for (int k = threadIdx.x; k < 5 * H; k += H) ps[k] = g_p[g * (5 * H) + k];
    __syncthreads();
    float acc = bl1[j];
    for (int k = 0; k < 5 * H; ++k) acc = fmaf(ps[k], Wl1[(size_t)k * (5 * H) + j], acc);
    g_q[g * (5 * H) + j] = fmaxf(acc, 0.f);
}

__global__ void k_mlp2(const float* __restrict__ Wl2, const float* __restrict__ bl2,
                       float* __restrict__ out) {
    __shared__ float red[H];
    int g = blockIdx.x, tid = threadIdx.x;
    float s = 0.f;
    for (int k = tid; k < 5 * H; k += H) s = fmaf(g_q[g * (5 * H) + k], Wl2[k], s);
    red[tid] = s;
    __syncthreads();
    for (int d = H / 2; d > 0; d >>= 1) {
        if (tid < d) red[tid] += red[tid + d];
        __syncthreads();
    }
    if (tid == 0) out[g] = red[0] + bl2[0];
}

// ---- launch ----
extern "C" void kernel_launch(void* const* d_in, const int* in_sizes, int n_in,
                              void* d_out, int out_size) {
    const float* x     = (const float*)d_in[0];
    const int*   edge  = (const int*)d_in[1];
    const int*   batch = (const int*)d_in[2];
    const float* W[5]  = {(const float*)d_in[3], (const float*)d_in[5],
                          (const float*)d_in[7], (const float*)d_in[9],
                          (const float*)d_in[9]};   // layer 5 reuses W4
    const float* B[5]  = {(const float*)d_in[4], (const float*)d_in[6],
                          (const float*)d_in[8], (const float*)d_in[10],
                          (const float*)d_in[10]};  // layer 5 reuses b4
    const float* Wl1 = (const float*)d_in[11];
    const float* bl1 = (const float*)d_in[12];
    const float* Wl2 = (const float*)d_in[13];
    const float* bl2 = (const float*)d_in[14];
    float* out = (float*)d_out;

    int n = in_sizes[0] / H;
    int E = in_sizes[1] / 2;
    const int* row = edge;       // sources
    const int* col = edge + E;   // targets

    float *hA, *hB, *tbuf;
    cudaGetSymbolAddress((void**)&hA, g_hA);
    cudaGetSymbolAddress((void**)&hB, g_hB);
    cudaGetSymbolAddress((void**)&tbuf, g_t);

    const int TB = 256;
    int initN = (n > NG + 1) ? n : (NG + 1);
    k_init<<<(initN + TB - 1) / TB, TB>>>(n);
    k_hist<<<(E + TB - 1) / TB, TB>>>(col, E);
    k_dinv<<<(n + TB - 1) / TB, TB>>>(n);
    k_scan<<<1, 1024>>>(n);
    k_scatter<<<(E + TB - 1) / TB, TB>>>(row, col, E);
    k_gmin<<<(n + TB - 1) / TB, TB>>>(batch, n);
    k_gfix<<<1, 1>>>();

    const float* hin = x;
    float* bufs[2] = {hA, hB};
    for (int l = 0; l < 5; ++l) {
        float* hout = bufs[l & 1];
        k_gemm<<<(n + 127) / 128, 256>>>(hin, W[l], tbuf, n);
        k_spmm<<<(n + 7) / 8, 256>>>(tbuf, B[l], hout, n);
        k_pool<<<NG, H>>>(hout, l * H);
        hin = hout;
    }
    k_mlp1<<<dim3(5, NG), H>>>(Wl1, bl1);
    k_mlp2<<<NG, H>>>(Wl2, bl2, out);
}

// round 2
// speedup vs baseline: 1.1706x; 1.1706x over previous
#include <cuda_runtime.h>

#define H 128
#define NMAX 100000
#define EMAX 1600000
#define NG 512
#define SCANB 1024

// ---- scratch (static __device__ globals; no allocation allowed) ----
__device__ float g_hA[(size_t)NMAX * H];
__device__ float g_hB[(size_t)NMAX * H];
__device__ float g_t[(size_t)NMAX * H];
__device__ float g_dinv[NMAX];
__device__ int   g_count[NMAX];
__device__ int   g_fill[NMAX];
__device__ int   g_rowptr[NMAX + 1];
__device__ int   g_src[EMAX];
__device__ int   g_gptr[NG + 1];
__device__ int   g_bsum[128];
__device__ int   g_boff[128];
__device__ float g_p[NG * 5 * H];
__device__ float g_q[NG * 5 * H];

// ---- preprocessing kernels ----
__global__ void k_init(int n) {
    int i = blockIdx.x * blockDim.x + threadIdx.x;
    if (i < n) { g_count[i] = 0; g_fill[i] = 0; }
    if (i <= NG) g_gptr[i] = n;
}

__global__ void k_hist(const int* __restrict__ col, int E) {
    int i = blockIdx.x * blockDim.x + threadIdx.x;
    if (i < E) atomicAdd(&g_count[col[i]], 1);
}

__global__ void k_dinv(int n) {
    int i = blockIdx.x * blockDim.x + threadIdx.x;
    if (i < n) g_dinv[i] = rsqrtf((float)(g_count[i] + 1));  // +1 self loop
}

// ---- decoupled 3-pass exclusive scan of g_count -> g_rowptr ----
__global__ __launch_bounds__(SCANB) void k_scan1(int n) {
    __shared__ int warpsum[32];
    int gid = blockIdx.x * SCANB + threadIdx.x;
    int lane = threadIdx.x & 31, wid = threadIdx.x >> 5;
    int v = (gid < n) ? g_count[gid] : 0;
    int x = v;
#pragma unroll
    for (int d = 1; d < 32; d <<= 1) {
        int t = __shfl_up_sync(0xffffffffu, x, d);
        if (lane >= d) x += t;
    }
    if (lane == 31) warpsum[wid] = x;
    __syncthreads();
    if (wid == 0) {
        int s = warpsum[lane];
#pragma unroll
        for (int d = 1; d < 32; d <<= 1) {
            int t = __shfl_up_sync(0xffffffffu, s, d);
            if (lane >= d) s += t;
        }
        warpsum[lane] = s;
    }
    __syncthreads();
    int excl = x - v + (wid > 0 ? warpsum[wid - 1] : 0);
    if (gid < n) g_rowptr[gid] = excl;
    if (threadIdx.x == SCANB - 1) g_bsum[blockIdx.x] = warpsum[31];
}

__global__ void k_scan2(int nb, int n) {   // nb <= 128, single block of 128
    __shared__ int warpsum[4];
    int tid = threadIdx.x;
    int lane = tid & 31, wid = tid >> 5;
    int v = (tid < nb) ? g_bsum[tid] : 0;
    int x = v;
#pragma unroll
    for (int d = 1; d < 32; d <<= 1) {
        int t = __shfl_up_sync(0xffffffffu, x, d);
        if (lane >= d) x += t;
    }
    if (lane == 31) warpsum[wid] = x;
    __syncthreads();
    int base = 0;
    for (int w = 0; w < wid; ++w) base += warpsum[w];
    g_boff[tid] = base + x - v;
    if (tid == 127) g_rowptr[n] = base + x;
}

__global__ __launch_bounds__(SCANB) void k_scan3(int n) {
    int gid = blockIdx.x * SCANB + threadIdx.x;
    if (gid < n) g_rowptr[gid] += g_boff[blockIdx.x];
}

__global__ void k_scatter(const int* __restrict__ row, const int* __restrict__ col, int E) {
    int i = blockIdx.x * blockDim.x + threadIdx.x;
    if (i < E) {
        int c = col[i];
        int pos = g_rowptr[c] + atomicAdd(&g_fill[c], 1);
        g_src[pos] = row[i];
    }
}

__global__ void k_gmin(const int* __restrict__ batch, int n) {
    int i = blockIdx.x * blockDim.x + threadIdx.x;
    if (i < n) atomicMin(&g_gptr[batch[i]], i);
}

__global__ void k_gfix() {
    for (int g = NG - 1; g >= 0; --g)
        if (g_gptr[g] > g_gptr[g + 1]) g_gptr[g] = g_gptr[g + 1];
}

// ---- GEMM: C[m,:] = dinv[m] * (A[m,:] @ W)  (dinv folded into epilogue) ----
__global__ __launch_bounds__(256) void k_gemm(const float* __restrict__ A,
                                              const float* __restrict__ W,
                                              float* __restrict__ C, int nrows) {
    __shared__ float As[128][33];
    __shared__ float Ws[32][H];
    int m0 = blockIdx.x * 128;
    int tid = threadIdx.x;
    int tx = tid & 15, ty = tid >> 4;

    float acc[8][8];
#pragma unroll
    for (int i = 0; i < 8; i++)
#pragma unroll
        for (int j = 0; j < 8; j++) acc[i][j] = 0.f;

    int lr = tid >> 3;          // 0..31
    int lc = (tid & 7) << 2;    // 0,4,...,28

    for (int k0 = 0; k0 < H; k0 += 32) {
#pragma unroll
        for (int p = 0; p < 4; p++) {
            int m = m0 + p * 32 + lr;
            float4 v = make_float4(0.f, 0.f, 0.f, 0.f);
            if (m < nrows) v = *(const float4*)&A[(size_t)m * H + k0 + lc];
            As[p * 32 + lr][lc + 0] = v.x;
            As[p * 32 + lr][lc + 1] = v.y;
            As[p * 32 + lr][lc + 2] = v.z;
            As[p * 32 + lr][lc + 3] = v.w;
        }
        {
            int wr = tid >> 5;          // 0..7
            int wc = (tid & 31) << 2;   // 0..124
#pragma unroll
            for (int p = 0; p < 4; p++) {
                int kk = p * 8 + wr;
                *(float4*)&Ws[kk][wc] = *(const float4*)&W[(size_t)(k0 + kk) * H + wc];
            }
        }
        __syncthreads();
#pragma unroll
        for (int kk = 0; kk < 32; ++kk) {
            float a[8], b[8];
#pragma unroll
            for (int i = 0; i < 8; i++) a[i] = As[ty * 8 + i][kk];
            float4 b0 = *(const float4*)&Ws[kk][tx * 8];
            float4 b1 = *(const float4*)&Ws[kk][tx * 8 + 4];
            b[0] = b0.x; b[1] = b0.y; b[2] = b0.z; b[3] = b0.w;
            b[4] = b1.x; b[5] = b1.y; b[6] = b1.z; b[7] = b1.w;
#pragma unroll
            for (int i = 0; i < 8; i++)
#pragma unroll
                for (int j = 0; j < 8; j++) acc[i][j] = fmaf(a[i], b[j], acc[i][j]);
        }
        __syncthreads();
    }
#pragma unroll
    for (int i = 0; i < 8; i++) {
        int m = m0 + ty * 8 + i;
        if (m < nrows) {
            float d = g_dinv[m];
            float4 v0 = make_float4(d * acc[i][0], d * acc[i][1], d * acc[i][2], d * acc[i][3]);
            float4 v1 = make_float4(d * acc[i][4], d * acc[i][5], d * acc[i][6], d * acc[i][7]);
            *(float4*)&C[(size_t)m * H + tx * 8] = v0;
            *(float4*)&C[(size_t)m * H + tx * 8 + 4] = v1;
        }
    }
}

// ---- SpMM: h[i] = relu(dinv[i]*(t[i] + sum_src t[src]) + b), t pre-scaled ----
__global__ __launch_bounds__(256) void k_spmm(const float* __restrict__ t,
                                              const float* __restrict__ bias,
                                              float* __restrict__ h, int n) {
    int warp = (blockIdx.x * blockDim.x + threadIdx.x) >> 5;
    if (warp >= n) return;
    int lane = threadIdx.x & 31;
    const float4* __restrict__ t4 = (const float4*)t;

    float di = g_dinv[warp];
    int e0 = g_rowptr[warp], e1 = g_rowptr[warp + 1];
    float4 self = t4[(size_t)warp * 32 + lane];
    float ax = self.x, ay = self.y, az = self.z, aw = self.w;
    float bx = 0.f, by = 0.f, bz = 0.f, bw = 0.f;
    int e = e0;
    for (; e + 1 < e1; e += 2) {
        int s0 = g_src[e];
        int s1 = g_src[e + 1];
        float4 v0 = t4[(size_t)s0 * 32 + lane];
        float4 v1 = t4[(size_t)s1 * 32 + lane];
        ax += v0.x; ay += v0.y; az += v0.z; aw += v0.w;
        bx += v1.x; by += v1.y; bz += v1.z; bw += v1.w;
    }
    if (e < e1) {
        int s = g_src[e];
        float4 v = t4[(size_t)s * 32 + lane];
        ax += v.x; ay += v.y; az += v.z; aw += v.w;
    }
    float4 b = ((const float4*)bias)[lane];
    float4 r;
    r.x = fmaxf(fmaf(di, ax + bx, b.x), 0.f);
    r.y = fmaxf(fmaf(di, ay + by, b.y), 0.f);
    r.z = fmaxf(fmaf(di, az + bz, b.z), 0.f);
    r.w = fmaxf(fmaf(di, aw + bw, b.w), 0.f);
    ((float4*)h)[(size_t)warp * 32 + lane] = r;
}

// ---- global mean pool (batch is sorted -> contiguous ranges) ----
__global__ void k_pool(const float* __restrict__ h, int off) {
    int g = blockIdx.x, tx = threadIdx.x;
    int s = g_gptr[g], e = g_gptr[g + 1];
    float sum = 0.f;
    for (int i = s; i < e; ++i) sum += h[(size_t)i * H + tx];
    int cnt = e - s;
    g_p[g * (5 * H) + off + tx] = sum / (float)(cnt > 0 ? cnt : 1);
}

// ---- MLP head ----
__global__ void k_mlp1(const float* __restrict__ Wl1, const float* __restrict__ bl1) {
    __shared__ float ps[5 * H];
    int g = blockIdx.y;
    int j = blockIdx.x * H + threadIdx.x;
    for (int k = threadIdx.x; k < 5 * H; k += H) ps[k] = g_p[g * (5 * H) + k];
    __syncthreads();
    float acc = bl1[j];
    for (int k = 0; k < 5 * H; ++k) acc = fmaf(ps[k], Wl1[(size_t)k * (5 * H) + j], acc);
    g_q[g * (5 * H) + j] = fmaxf(acc, 0.f);
}

__global__ void k_mlp2(const float* __restrict__ Wl2, const float* __restrict__ bl2,
                       float* __restrict__ out) {
    __shared__ float red[H];
    int g = blockIdx.x, tid = threadIdx.x;
    float s = 0.f;
    for (int k = tid; k < 5 * H; k += H) s = fmaf(g_q[g * (5 * H) + k], Wl2[k], s);
    red[tid] = s;
    __syncthreads();
    for (int d = H / 2; d > 0; d >>= 1) {
        if (tid < d) red[tid] += red[tid + d];
        __syncthreads();
    }
    if (tid == 0) out[g] = red[0] + bl2[0];
}

// ---- launch ----
extern "C" void kernel_launch(void* const* d_in, const int* in_sizes, int n_in,
                              void* d_out, int out_size) {
    const float* x     = (const float*)d_in[0];
    const int*   edge  = (const int*)d_in[1];
    const int*   batch = (const int*)d_in[2];
    const float* W[5]  = {(const float*)d_in[3], (const float*)d_in[5],
                          (const float*)d_in[7], (const float*)d_in[9],
                          (const float*)d_in[9]};   // layer 5 reuses W4
    const float* B[5]  = {(const float*)d_in[4], (const float*)d_in[6],
                          (const float*)d_in[8], (const float*)d_in[10],
                          (const float*)d_in[10]};  // layer 5 reuses b4
    const float* Wl1 = (const float*)d_in[11];
    const float* bl1 = (const float*)d_in[12];
    const float* Wl2 = (const float*)d_in[13];
    const float* bl2 = (const float*)d_in[14];
    float* out = (float*)d_out;

    int n = in_sizes[0] / H;
    int E = in_sizes[1] / 2;
    const int* row = edge;       // sources
    const int* col = edge + E;   // targets

    float *hA, *hB, *tbuf;
    cudaGetSymbolAddress((void**)&hA, g_hA);
    cudaGetSymbolAddress((void**)&hB, g_hB);
    cudaGetSymbolAddress((void**)&tbuf, g_t);

    const int TB = 256;
    int nbScan = (n + SCANB - 1) / SCANB;
    int initN = (n > NG + 1) ? n : (NG + 1);
    k_init<<<(initN + TB - 1) / TB, TB>>>(n);
    k_hist<<<(E + TB - 1) / TB, TB>>>(col, E);
    k_dinv<<<(n + TB - 1) / TB, TB>>>(n);
    k_scan1<<<nbScan, SCANB>>>(n);
    k_scan2<<<1, 128>>>(nbScan, n);
    k_scan3<<<nbScan, SCANB>>>(n);
    k_scatter<<<(E + TB - 1) / TB, TB>>>(row, col, E);
    k_gmin<<<(n + TB - 1) / TB, TB>>>(batch, n);
    k_gfix<<<1, 1>>>();

    const float* hin = x;
    float* bufs[2] = {hA, hB};
    for (int l = 0; l < 5; ++l) {
        float* hout = bufs[l & 1];
        k_gemm<<<(n + 127) / 128, 256>>>(hin, W[l], tbuf, n);
        k_spmm<<<(n + 7) / 8, 256>>>(tbuf, B[l], hout, n);
        k_pool<<<NG, H>>>(hout, l * H);
        hin = hout;
    }
    k_mlp1<<<dim3(5, NG), H>>>(Wl1, bl1);
    k_mlp2<<<NG, H>>>(Wl2, bl2, out);
}

// round 4
// speedup vs baseline: 1.2425x; 1.0614x over previous
#include <cuda_runtime.h>
#include <cuda_bf16.h>
#include <cstdint>

#define H 128
#define NMAX 100000
#define EMAX 1600000
#define NG 512
#define SCANB 1024

// ---- scratch (static __device__ globals; no allocation allowed) ----
__device__ float g_hA[(size_t)NMAX * H];
__device__ float g_hB[(size_t)NMAX * H];
__device__ float g_t[(size_t)NMAX * H];
__device__ float g_dinv[NMAX];
__device__ int   g_count[NMAX];
__device__ int   g_fill[NMAX];
__device__ int   g_rowptr[NMAX + 1];
__device__ int   g_src[EMAX];
__device__ int   g_gptr[NG + 1];
__device__ int   g_bsum[128];
__device__ int   g_boff[128];
__device__ float g_p[NG * 5 * H];
__device__ float g_q[NG * 5 * H];
// bf16 hi/lo weight images, k-major [128][136] padded rows (272 B)
#define WBYTES (128 * 136 * 2)
__device__ __align__(16) unsigned char g_whi[4][WBYTES];
__device__ __align__(16) unsigned char g_wlo[4][WBYTES];

__device__ __forceinline__ uint32_t smem_u32(const void* p) {
    uint32_t a;
    asm("{ .reg .u64 t; cvta.to.shared.u64 t, %1; cvt.u32.u64 %0, t; }" : "=r"(a) : "l"(p));
    return a;
}

#define LDSM_X4(r, addr) \
    asm volatile("ldmatrix.sync.aligned.m8n8.x4.shared.b16 {%0,%1,%2,%3}, [%4];" \
        : "=r"((r)[0]), "=r"((r)[1]), "=r"((r)[2]), "=r"((r)[3]) : "r"(addr))
#define LDSM_X4_T(r, addr) \
    asm volatile("ldmatrix.sync.aligned.m8n8.x4.trans.shared.b16 {%0,%1,%2,%3}, [%4];" \
        : "=r"((r)[0]), "=r"((r)[1]), "=r"((r)[2]), "=r"((r)[3]) : "r"(addr))
#define MMA_BF16(c, a, b0, b1) \
    asm volatile("mma.sync.aligned.m16n8k16.row.col.f32.bf16.bf16.f32 " \
        "{%0,%1,%2,%3}, {%4,%5,%6,%7}, {%8,%9}, {%0,%1,%2,%3};" \
        : "+f"((c)[0]), "+f"((c)[1]), "+f"((c)[2]), "+f"((c)[3]) \
        : "r"((a)[0]), "r"((a)[1]), "r"((a)[2]), "r"((a)[3]), "r"(b0), "r"(b1))

__device__ __forceinline__ uint32_t pack2(float a, float b) {
    uint32_t lo = __bfloat16_as_ushort(__float2bfloat16_rn(a));
    uint32_t hi = __bfloat16_as_ushort(__float2bfloat16_rn(b));
    return lo | (hi << 16);
}

// ---- preprocessing kernels ----
__global__ void k_init(int n) {
    int i = blockIdx.x * blockDim.x + threadIdx.x;
    if (i < n) { g_count[i] = 0; g_fill[i] = 0; }
    if (i <= NG) g_gptr[i] = n;
}

__global__ void k_hist(const int* __restrict__ col, int E) {
    int i = blockIdx.x * blockDim.x + threadIdx.x;
    if (i < E) atomicAdd(&g_count[col[i]], 1);
}

__global__ void k_dinv(int n) {
    int i = blockIdx.x * blockDim.x + threadIdx.x;
    if (i < n) g_dinv[i] = rsqrtf((float)(g_count[i] + 1));
}

__global__ __launch_bounds__(SCANB) void k_scan1(int n) {
    __shared__ int warpsum[32];
    int gid = blockIdx.x * SCANB + threadIdx.x;
    int lane = threadIdx.x & 31, wid = threadIdx.x >> 5;
    int v = (gid < n) ? g_count[gid] : 0;
    int x = v;
#pragma unroll
    for (int d = 1; d < 32; d <<= 1) {
        int t = __shfl_up_sync(0xffffffffu, x, d);
        if (lane >= d) x += t;
    }
    if (lane == 31) warpsum[wid] = x;
    __syncthreads();
    if (wid == 0) {
        int s = warpsum[lane];
#pragma unroll
        for (int d = 1; d < 32; d <<= 1) {
            int t = __shfl_up_sync(0xffffffffu, s, d);
            if (lane >= d) s += t;
        }
        warpsum[lane] = s;
    }
    __syncthreads();
    int excl = x - v + (wid > 0 ? warpsum[wid - 1] : 0);
    if (gid < n) g_rowptr[gid] = excl;
    if (threadIdx.x == SCANB - 1) g_bsum[blockIdx.x] = warpsum[31];
}

__global__ void k_scan2(int nb, int n) {
    __shared__ int warpsum[4];
    int tid = threadIdx.x;
    int lane = tid & 31, wid = tid >> 5;
    int v = (tid < nb) ? g_bsum[tid] : 0;
    int x = v;
#pragma unroll
    for (int d = 1; d < 32; d <<= 1) {
        int t = __shfl_up_sync(0xffffffffu, x, d);
        if (lane >= d) x += t;
    }
    if (lane == 31) warpsum[wid] = x;
    __syncthreads();
    int base = 0;
    for (int w = 0; w < wid; ++w) base += warpsum[w];
    g_boff[tid] = base + x - v;
    if (tid == 127) g_rowptr[n] = base + x;
}

__global__ __launch_bounds__(SCANB) void k_scan3(int n) {
    int gid = blockIdx.x * SCANB + threadIdx.x;
    if (gid < n) g_rowptr[gid] += g_boff[blockIdx.x];
}

__global__ void k_scatter(const int* __restrict__ row, const int* __restrict__ col, int E) {
    int i = blockIdx.x * blockDim.x + threadIdx.x;
    if (i < E) {
        int c = col[i];
        int pos = g_rowptr[c] + atomicAdd(&g_fill[c], 1);
        g_src[pos] = row[i];
    }
}

__global__ void k_gmin(const int* __restrict__ batch, int n) {
    int i = blockIdx.x * blockDim.x + threadIdx.x;
    if (i < n) atomicMin(&g_gptr[batch[i]], i);
}

__global__ void k_gfix() {
    for (int g = NG - 1; g >= 0; --g)
        if (g_gptr[g] > g_gptr[g + 1]) g_gptr[g] = g_gptr[g + 1];
}

// ---- weight prep: split fp32 W[k][n] into bf16 hi/lo, k-major padded rows ----
__global__ void k_wprep(const float* __restrict__ W0, const float* __restrict__ W1,
                        const float* __restrict__ W2, const float* __restrict__ W3) {
    const float* Ws[4] = {W0, W1, W2, W3};
    int layer = blockIdx.y;
    int idx = blockIdx.x * blockDim.x + threadIdx.x;   // 0..16383
    int k = idx >> 7, nn = idx & 127;
    float w = Ws[layer][idx];
    __nv_bfloat16 hb = __float2bfloat16_rn(w);
    float lres = w - __bfloat162float(hb);
    __nv_bfloat16 lb = __float2bfloat16_rn(lres);
    uint32_t off = (uint32_t)(k * 136 + nn) * 2;
    *(unsigned short*)&g_whi[layer][off] = __bfloat16_as_ushort(hb);
    *(unsigned short*)&g_wlo[layer][off] = __bfloat16_as_ushort(lb);
}

// ---- HMMA GEMM: C[m,:] = dinv[m] * (A[m,:] @ W), bf16-split 3 passes ----
#define SM_AHI 0
#define SM_ALO 34816
#define SM_WHI 69632
#define SM_WLO 104448
#define SM_TOTAL 139264

__global__ __launch_bounds__(256) void k_gemm_mma(const float* __restrict__ A,
                                                  const unsigned char* __restrict__ Whi,
                                                  const unsigned char* __restrict__ Wlo,
                                                  float* __restrict__ C, int nrows) {
    extern __shared__ char smem[];
    uint32_t sb = smem_u32(smem);
    int tid = threadIdx.x, lane = tid & 31, wid = tid >> 5;
    int wm = wid >> 1, wn = wid & 1;      // 4x2 warp grid; warp tile 32x64
    int m0 = blockIdx.x * 128;

    // copy pre-split W images (layout identical, straight byte copy)
    {
        const uint4* __restrict__ s1 = (const uint4*)Whi;
        const uint4* __restrict__ s2 = (const uint4*)Wlo;
        uint4* d1 = (uint4*)(smem + SM_WHI);
        uint4* d2 = (uint4*)(smem + SM_WLO);
        for (int i = tid; i < WBYTES / 16; i += 256) { d1[i] = s1[i]; d2[i] = s2[i]; }
    }
    // load A tile, split to bf16 hi/lo, padded row-major [128][136]
    for (int i = tid; i < 128 * 32; i += 256) {
        int row = i >> 5, c4 = i & 31;
        int m = m0 + row;
        float4 v = make_float4(0.f, 0.f, 0.f, 0.f);
        if (m < nrows) v = *(const float4*)&A[(size_t)m * H + c4 * 4];
        __nv_bfloat16 hx = __float2bfloat16_rn(v.x);
        __nv_bfloat16 hy = __float2bfloat16_rn(v.y);
        __nv_bfloat16 hz = __float2bfloat16_rn(v.z);
        __nv_bfloat16 hw = __float2bfloat16_rn(v.w);
        uint2 hp, lp;
        hp.x = (uint32_t)__bfloat16_as_ushort(hx) | ((uint32_t)__bfloat16_as_ushort(hy) << 16);
        hp.y = (uint32_t)__bfloat16_as_ushort(hz) | ((uint32_t)__bfloat16_as_ushort(hw) << 16);
        lp.x = pack2(v.x - __bfloat162float(hx), v.y - __bfloat162float(hy));
        lp.y = pack2(v.z - __bfloat162float(hz), v.w - __bfloat162float(hw));
        uint32_t off = (uint32_t)row * 272 + (uint32_t)c4 * 8;
        *(uint2*)(smem + SM_AHI + off) = hp;
        *(uint2*)(smem + SM_ALO + off) = lp;
    }
    __syncthreads();

    float c[2][8][4];
#pragma unroll
    for (int mi = 0; mi < 2; ++mi)
#pragma unroll
        for (int nj = 0; nj < 8; ++nj)
#pragma unroll
            for (int q = 0; q < 4; ++q) c[mi][nj][q] = 0.f;

#pragma unroll
    for (int p = 0; p < 3; ++p) {
        uint32_t aBase = sb + (p == 2 ? SM_ALO : SM_AHI);
        uint32_t wBase = sb + (p == 1 ? SM_WLO : SM_WHI);
        // A: row = wm*32 + mi*16 + (lane&15), colbyte = kc*32 + (lane>>4)*16
        uint32_t aAddr = aBase + (uint32_t)(wm * 32 + (lane & 15)) * 272 + (uint32_t)(lane >> 4) * 16;
        // B: krow = kc*16 + (lane&15), colbyte = wn*128 + ni*32 + (lane>>4)*16
        uint32_t bAddr = wBase + (uint32_t)(lane & 15) * 272 + (uint32_t)(wn * 128) + (uint32_t)(lane >> 4) * 16;
#pragma unroll
        for (int kc = 0; kc < 8; ++kc) {
            uint32_t a[2][4];
            LDSM_X4(a[0], aAddr + kc * 32);
            LDSM_X4(a[1], aAddr + 16 * 272 + kc * 32);
            uint32_t b[4][4];
#pragma unroll
            for (int ni = 0; ni < 4; ++ni)
                LDSM_X4_T(b[ni], bAddr + (uint32_t)kc * 16 * 272 + (uint32_t)ni * 32);
#pragma unroll
            for (int mi = 0; mi < 2; ++mi)
#pragma unroll
                for (int ni = 0; ni < 4; ++ni) {
                    MMA_BF16(c[mi][2 * ni],     a[mi], b[ni][0], b[ni][1]);
                    MMA_BF16(c[mi][2 * ni + 1], a[mi], b[ni][2], b[ni][3]);
                }
        }
    }

    // epilogue: scale by dinv, store straight from fragments
#pragma unroll
    for (int mi = 0; mi < 2; ++mi) {
        int r = m0 + wm * 32 + mi * 16 + (lane >> 2);
        int r8 = r + 8;
        float d0 = (r < nrows) ? g_dinv[r] : 0.f;
        float d8 = (r8 < nrows) ? g_dinv[r8] : 0.f;
#pragma unroll
        for (int nj = 0; nj < 8; ++nj) {
            int col = wn * 64 + nj * 8 + (lane & 3) * 2;
            if (r < nrows) {
                float2 o = make_float2(d0 * c[mi][nj][0], d0 * c[mi][nj][1]);
                *(float2*)&C[(size_t)r * H + col] = o;
            }
            if (r8 < nrows) {
                float2 o = make_float2(d8 * c[mi][nj][2], d8 * c[mi][nj][3]);
                *(float2*)&C[(size_t)r8 * H + col] = o;
            }
        }
    }
}

// ---- SpMM: h[i] = relu(dinv[i]*(t[i] + sum_src t[src]) + b), t pre-scaled ----
__global__ __launch_bounds__(256) void k_spmm(const float* __restrict__ t,
                                              const float* __restrict__ bias,
                                              float* __restrict__ h, int n) {
    int warp = (blockIdx.x * blockDim.x + threadIdx.x) >> 5;
    if (warp >= n) return;
    int lane = threadIdx.x & 31;
    const float4* __restrict__ t4 = (const float4*)t;

    float di = g_dinv[warp];
    int e0 = g_rowptr[warp], e1 = g_rowptr[warp + 1];
    float4 self = t4[(size_t)warp * 32 + lane];
    float ax = self.x, ay = self.y, az = self.z, aw = self.w;
    float bx = 0.f, by = 0.f, bz = 0.f, bw = 0.f;
    int e = e0;
    for (; e + 1 < e1; e += 2) {
        int s0 = g_src[e];
        int s1 = g_src[e + 1];
        float4 v0 = t4[(size_t)s0 * 32 + lane];
        float4 v1 = t4[(size_t)s1 * 32 + lane];
        ax += v0.x; ay += v0.y; az += v0.z; aw += v0.w;
        bx += v1.x; by += v1.y; bz += v1.z; bw += v1.w;
    }
    if (e < e1) {
        int s = g_src[e];
        float4 v = t4[(size_t)s * 32 + lane];
        ax += v.x; ay += v.y; az += v.z; aw += v.w;
    }
    float4 b = ((const float4*)bias)[lane];
    float4 r;
    r.x = fmaxf(fmaf(di, ax + bx, b.x), 0.f);
    r.y = fmaxf(fmaf(di, ay + by, b.y), 0.f);
    r.z = fmaxf(fmaf(di, az + bz, b.z), 0.f);
    r.w = fmaxf(fmaf(di, aw + bw, b.w), 0.f);
    ((float4*)h)[(size_t)warp * 32 + lane] = r;
}

// ---- global mean pool ----
__global__ void k_pool(const float* __restrict__ h, int off) {
    int g = blockIdx.x, tx = threadIdx.x;
    int s = g_gptr[g], e = g_gptr[g + 1];
    float sum = 0.f;
    for (int i = s; i < e; ++i) sum += h[(size_t)i * H + tx];
    int cnt = e - s;
    g_p[g * (5 * H) + off + tx] = sum / (float)(cnt > 0 ? cnt : 1);
}

// ---- MLP head ----
__global__ void k_mlp1(const float* __restrict__ Wl1, const float* __restrict__ bl1) {
    __shared__ float ps[5 * H];
    int g = blockIdx.y;
    int j = blockIdx.x * H + threadIdx.x;
    for (int k = threadIdx.x; k < 5 * H; k += H) ps[k] = g_p[g * (5 * H) + k];
    __syncthreads();
    float acc = bl1[j];
    for (int k = 0; k < 5 * H; ++k) acc = fmaf(ps[k], Wl1[(size_t)k * (5 * H) + j], acc);
    g_q[g * (5 * H) + j] = fmaxf(acc, 0.f);
}

__global__ void k_mlp2(const float* __restrict__ Wl2, const float* __restrict__ bl2,
                       float* __restrict__ out) {
    __shared__ float red[H];
    int g = blockIdx.x, tid = threadIdx.x;
    float s = 0.f;
    for (int k = tid; k < 5 * H; k += H) s = fmaf(g_q[g * (5 * H) + k], Wl2[k], s);
    red[tid] = s;
    __syncthreads();
    for (int d = H / 2; d > 0; d >>= 1) {
        if (tid < d) red[tid] += red[tid + d];
        __syncthreads();
    }
    if (tid == 0) out[g] = red[0] + bl2[0];
}

// ---- launch ----
extern "C" void kernel_launch(void* const* d_in, const int* in_sizes, int n_in,
                              void* d_out, int out_size) {
    const float* x     = (const float*)d_in[0];
    const int*   edge  = (const int*)d_in[1];
    const int*   batch = (const int*)d_in[2];
    const float* B[5]  = {(const float*)d_in[4], (const float*)d_in[6],
                          (const float*)d_in[8], (const float*)d_in[10],
                          (const float*)d_in[10]};  // layer 5 reuses b4
    const float* Wl1 = (const float*)d_in[11];
    const float* bl1 = (const float*)d_in[12];
    const float* Wl2 = (const float*)d_in[13];
    const float* bl2 = (const float*)d_in[14];
    float* out = (float*)d_out;

    int n = in_sizes[0] / H;
    int E = in_sizes[1] / 2;
    const int* row = edge;       // sources
    const int* col = edge + E;   // targets

    float *hA, *hB, *tbuf;
    cudaGetSymbolAddress((void**)&hA, g_hA);
    cudaGetSymbolAddress((void**)&hB, g_hB);
    cudaGetSymbolAddress((void**)&tbuf, g_t);
    unsigned char *whi, *wlo;
    cudaGetSymbolAddress((void**)&whi, g_whi);
    cudaGetSymbolAddress((void**)&wlo, g_wlo);

    cudaFuncSetAttribute(k_gemm_mma, cudaFuncAttributeMaxDynamicSharedMemorySize, SM_TOTAL);

    const int TB = 256;
    int nbScan = (n + SCANB - 1) / SCANB;
    int initN = (n > NG + 1) ? n : (NG + 1);
    k_init<<<(initN + TB - 1) / TB, TB>>>(n);
    k_hist<<<(E + TB - 1) / TB, TB>>>(col, E);
    k_dinv<<<(n + TB - 1) / TB, TB>>>(n);
    k_scan1<<<nbScan, SCANB>>>(n);
    k_scan2<<<1, 128>>>(nbScan, n);
    k_scan3<<<nbScan, SCANB>>>(n);
    k_scatter<<<(E + TB - 1) / TB, TB>>>(row, col, E);
    k_gmin<<<(n + TB - 1) / TB, TB>>>(batch, n);
    k_gfix<<<1, 1>>>();
    k_wprep<<<dim3(64, 4), 256>>>((const float*)d_in[3], (const float*)d_in[5],
                                  (const float*)d_in[7], (const float*)d_in[9]);

    const float* hin = x;
    float* bufs[2] = {hA, hB};
    int tiles = (n + 127) / 128;
    for (int l = 0; l < 5; ++l) {
        float* hout = bufs[l & 1];
        int widx = (l < 4) ? l : 3;   // layer 5 reuses W4
        k_gemm_mma<<<tiles, 256, SM_TOTAL>>>(hin, whi + (size_t)widx * WBYTES,
                                             wlo + (size_t)widx * WBYTES, tbuf, n);
        k_spmm<<<(n + 7) / 8, 256>>>(tbuf, B[l], hout, n);
        k_pool<<<NG, H>>>(hout, l * H);
        hin = hout;
    }
    k_mlp1<<<dim3(5, NG), H>>>(Wl1, bl1);
    k_mlp2<<<NG, H>>>(Wl2, bl2, out);
}